// round 11
// baseline (speedup 1.0000x reference)
#include <cuda_runtime.h>
#include <cuda_fp16.h>
#include <cstdint>

// ---------------- problem constants ----------------
#define DD 2048
#define HH 2048
#define KK 4096

// ---------------- scratch (device globals; no allocation allowed) ----------
__device__ __half g_hA[(size_t)KK * HH];        // children_h in fp16 (16MB)
__device__ __half g_hB[(size_t)HH * HH];        // W_fh in fp16 (8MB)
__device__ float  g_hsum_part[128][HH];
__device__ float  g_iou[3 * HH];
__device__ float  g_fx[HH];
__device__ float  g_cpart[32][HH];              // per-M-tile partial c sums
__device__ int    g_flags[64];                  // gemv strip ready flags
__device__ int    g_cnt[16];                    // per-bx completion counters

// ---------------- PTX helpers ----------------
__device__ __forceinline__ uint32_t smem_u32(const void* p) {
    uint32_t a;
    asm("{ .reg .u64 t; cvta.to.shared.u64 t, %1; cvt.u32.u64 %0, t; }" : "=r"(a) : "l"(p));
    return a;
}

#define CP_ASYNC16(dst, src) \
    asm volatile("cp.async.cg.shared.global [%0], [%1], 16;" :: "r"(dst), "l"(src))
#define CP_COMMIT() asm volatile("cp.async.commit_group;")
#define CP_WAIT(n)  asm volatile("cp.async.wait_group %0;" :: "n"(n))

#define LDSM_X4(r0, r1, r2, r3, addr) \
    asm volatile("ldmatrix.sync.aligned.m8n8.x4.shared.b16 {%0,%1,%2,%3}, [%4];" \
        : "=r"(r0), "=r"(r1), "=r"(r2), "=r"(r3) : "r"(addr))

#define MMA16816(d, a, b0, b1) \
    asm volatile("mma.sync.aligned.m16n8k16.row.col.f32.f16.f16.f32 " \
        "{%0,%1,%2,%3},{%4,%5,%6,%7},{%8,%9},{%0,%1,%2,%3};" \
        : "+f"((d)[0]), "+f"((d)[1]), "+f"((d)[2]), "+f"((d)[3]) \
        : "r"((a)[0]), "r"((a)[1]), "r"((a)[2]), "r"((a)[3]), "r"(b0), "r"(b1))

// ============================================================================
// Kernel 1: merged prep, 2048 blocks.
//  by < 128 : column-sum partials of children_h (32-row strips) + fp16 convert
//  by >= 128: W_fh fp32->fp16 convert (1024 blocks, 4 float4/thread)
// grid (8, 256), 256 threads
// ============================================================================
__global__ __launch_bounds__(256) void k_prep(const float* __restrict__ ch,
                                              const float* __restrict__ W) {
    int t = threadIdx.x;
    if (blockIdx.y < 128) {
        int cs = blockIdx.x, rs = blockIdx.y;
        int tx = t & 63, ty = t >> 6;
        int col = cs * 256 + tx * 4;
        int row0 = rs * 32 + ty * 8;
        float4 acc = make_float4(0.f, 0.f, 0.f, 0.f);
#pragma unroll
        for (int r = 0; r < 8; r++) {
            size_t off = (size_t)(row0 + r) * HH + col;
            float4 v = *reinterpret_cast<const float4*>(ch + off);
            acc.x += v.x; acc.y += v.y; acc.z += v.z; acc.w += v.w;
            union { __half2 h2[2]; uint2 u; } cv;
            cv.h2[0] = __floats2half2_rn(v.x, v.y);
            cv.h2[1] = __floats2half2_rn(v.z, v.w);
            *reinterpret_cast<uint2*>(g_hA + off) = cv.u;
        }
        __shared__ float sp[4][256];
        sp[ty][tx * 4 + 0] = acc.x;
        sp[ty][tx * 4 + 1] = acc.y;
        sp[ty][tx * 4 + 2] = acc.z;
        sp[ty][tx * 4 + 3] = acc.w;
        __syncthreads();
        float s = sp[0][t] + sp[1][t] + sp[2][t] + sp[3][t];
        g_hsum_part[rs][cs * 256 + t] = s;
    } else {
        int pb = blockIdx.x + 8 * (blockIdx.y - 128);    // 0..1023
        if (pb == 0 && t < 80) {
            if (t < 64) g_flags[t] = 0;
            else        g_cnt[t - 64] = 0;
        }
#pragma unroll
        for (int k = 0; k < 4; k++) {
            int i = pb * 1024 + k * 256 + t;
            float4 v = reinterpret_cast<const float4*>(W)[i];
            union { __half2 h2[2]; uint2 u; } cv;
            cv.h2[0] = __floats2half2_rn(v.x, v.y);
            cv.h2[1] = __floats2half2_rn(v.z, v.w);
            reinterpret_cast<uint2*>(g_hB)[i] = cv.u;
        }
    }
}

// ============================================================================
// Kernel 2: HMMA fp16 GEMM fh = children_h @ W_fh^T fused with
//   c_partial[n] += sum_m sigmoid(fx+b_fh+fh[m][n]) * children_c[m][n]
// BM=128, BN=128, BK=64 swizzled (R10), but 1 CTA/SM (255-reg cap) with
// EXPLICIT FRAGMENT DOUBLE-BUFFERING in the kk loop so LDSM (smem crossbar)
// overlaps HMMA (tensor pipe) via ILP instead of the serialization seen at
// the 128-reg cap. NST=4 stages of 32KB. Grid (16 nT, 32 mT).
// First 64 CTAs (by<4) run the embedded GEMV producer prologue; last
// finisher per bx (counter==31) runs the final combine + output write.
// ============================================================================
#define STB 32768                    // stage bytes: A 16KB + B 16KB
#define NST 4
#define SRED_OFF (NST * STB)         // 131072
#define FXS_OFF  (SRED_OFF + 4 * 128 * 4)
#define SMEM_TOTAL_G (FXS_OFF + 128 * 4)

__global__ __launch_bounds__(256, 1) void k_gemm(const float* __restrict__ children_c,
                                                 const float* __restrict__ bfh,
                                                 const float* __restrict__ input,
                                                 const float* __restrict__ Wix,
                                                 const float* __restrict__ bix,
                                                 const float* __restrict__ Wih,
                                                 const float* __restrict__ bih,
                                                 const float* __restrict__ Wfx,
                                                 const float* __restrict__ bfx,
                                                 float* __restrict__ out) {
    extern __shared__ __align__(1024) char smem[];
    __shared__ int s_old;
    uint32_t smb = smem_u32(smem);
    int t = threadIdx.x;
    int lane = t & 31, wid = t >> 5;
    int wm = wid & 3, wn = wid >> 2;
    int n0 = blockIdx.x * 128;
    int m0 = blockIdx.y * 128;

    // ------------- embedded GEMV producer prologue -------------
    if (blockIdx.y < 4) {
        int p = blockIdx.x + 16 * blockIdx.y;            // strip 0..63
        float* s_vec = reinterpret_cast<float*>(smem);   // input  [0,2048)
        float* s_hv  = reinterpret_cast<float*>(smem) + 2048;
        for (int i = t; i < 512; i += 256)
            reinterpret_cast<float4*>(s_vec)[i] = reinterpret_cast<const float4*>(input)[i];
        bool is_iou = (p < 48);
        if (is_iou) {
            for (int c = t; c < 2048; c += 256) {
                float s = 0.f;
#pragma unroll
                for (int r = 0; r < 128; r++) s += g_hsum_part[r][c];
                s_hv[c] = s;
            }
        }
        __syncthreads();
        int rbase = p * 128 + wid * 16;
        const float4* xi = reinterpret_cast<const float4*>(s_vec);
        const float4* xh = reinterpret_cast<const float4*>(s_hv);
#pragma unroll 1
        for (int rr = 0; rr < 16; rr += 2) {
            int R = rbase + rr;
            float acc0 = 0.f, acc1 = 0.f;
            if (is_iou) {
                const float4* w1a = reinterpret_cast<const float4*>(Wix + (size_t)R * DD);
                const float4* w1b = reinterpret_cast<const float4*>(Wix + (size_t)(R + 1) * DD);
                const float4* w2a = reinterpret_cast<const float4*>(Wih + (size_t)R * HH);
                const float4* w2b = reinterpret_cast<const float4*>(Wih + (size_t)(R + 1) * HH);
#pragma unroll
                for (int q = 0; q < 16; q++) {
                    float4 b = xi[q * 32 + lane];
                    float4 a0 = w1a[q * 32 + lane];
                    float4 a1 = w1b[q * 32 + lane];
                    acc0 += a0.x * b.x + a0.y * b.y + a0.z * b.z + a0.w * b.w;
                    acc1 += a1.x * b.x + a1.y * b.y + a1.z * b.z + a1.w * b.w;
                }
#pragma unroll
                for (int q = 0; q < 16; q++) {
                    float4 b = xh[q * 32 + lane];
                    float4 a0 = w2a[q * 32 + lane];
                    float4 a1 = w2b[q * 32 + lane];
                    acc0 += a0.x * b.x + a0.y * b.y + a0.z * b.z + a0.w * b.w;
                    acc1 += a1.x * b.x + a1.y * b.y + a1.z * b.z + a1.w * b.w;
                }
            } else {
                int j = R - 3 * HH;
                const float4* wa = reinterpret_cast<const float4*>(Wfx + (size_t)j * DD);
                const float4* wb = reinterpret_cast<const float4*>(Wfx + (size_t)(j + 1) * DD);
#pragma unroll
                for (int q = 0; q < 16; q++) {
                    float4 b = xi[q * 32 + lane];
                    float4 a0 = wa[q * 32 + lane];
                    float4 a1 = wb[q * 32 + lane];
                    acc0 += a0.x * b.x + a0.y * b.y + a0.z * b.z + a0.w * b.w;
                    acc1 += a1.x * b.x + a1.y * b.y + a1.z * b.z + a1.w * b.w;
                }
            }
#pragma unroll
            for (int off = 16; off; off >>= 1) {
                acc0 += __shfl_xor_sync(0xFFFFFFFFu, acc0, off);
                acc1 += __shfl_xor_sync(0xFFFFFFFFu, acc1, off);
            }
            if (lane == 0) {
                if (is_iou) {
                    g_iou[R]     = acc0 + bix[R] + bih[R];
                    g_iou[R + 1] = acc1 + bix[R + 1] + bih[R + 1];
                } else {
                    int j = R - 3 * HH;
                    g_fx[j]     = acc0 + bfx[j];
                    g_fx[j + 1] = acc1 + bfx[j + 1];
                }
            }
        }
        __threadfence();
        __syncthreads();
        if (t == 0) atomicExch(&g_flags[p], 1);
        __syncthreads();      // smem about to be reused by pipeline
    }

    // ------------- MMA mainloop (BK=64, swizzled 128B rows) -------------
    int rx = lane & 7;                 // row & 7 for all fragment rows
    int cA = lane >> 4;                // A: which 16B half of k16
    int cB = (lane >> 3) & 1;          // B: which 16B half of k16

    uint32_t aroff[2], broff[4];
#pragma unroll
    for (int mf = 0; mf < 2; mf++)
        aroff[mf] = (uint32_t)((wm * 32 + mf * 16 + (lane & 15)) << 7);
#pragma unroll
    for (int g = 0; g < 4; g++)
        broff[g] = (uint32_t)(16384 + ((wn * 64 + g * 16 + ((lane >> 4) << 3) + (lane & 7)) << 7));

    auto issue_load = [&](int ci, int s) {
        uint32_t st = smb + s * STB;
#pragma unroll
        for (int j = 0; j < 4; j++) {
            int idx = j * 256 + t;
            int r = idx >> 3, c = idx & 7;
            uint32_t off = (uint32_t)(r << 7) + (uint32_t)(((c ^ (r & 7))) << 4);
            const __half* srcA = g_hA + (size_t)(m0 + r) * HH + ci * 64 + c * 8;
            CP_ASYNC16(st + off, __cvta_generic_to_global(srcA));
            const __half* srcB = g_hB + (size_t)(n0 + r) * HH + ci * 64 + c * 8;
            CP_ASYNC16(st + 16384 + off, __cvta_generic_to_global(srcB));
        }
        CP_COMMIT();
    };

    float acc[2][8][4];
#pragma unroll
    for (int mf = 0; mf < 2; mf++)
#pragma unroll
        for (int nf = 0; nf < 8; nf++)
#pragma unroll
            for (int q = 0; q < 4; q++) acc[mf][nf][q] = 0.f;

    issue_load(0, 0);
    issue_load(1, 1);
    issue_load(2, 2);

    // double-buffered fragments (ILP pipeline: load kk+1 while MMA kk)
    uint32_t ar[2][2][4];
    uint32_t br[2][4][4];

    for (int ci = 0; ci < 32; ci++) {
        int s = ci & 3;
        CP_WAIT(2);
        __syncthreads();
        if (ci + 3 < 32) issue_load(ci + 3, (ci + 3) & 3);
        else CP_COMMIT();

        uint32_t stb = smb + (uint32_t)s * STB;

        // preload kk=0 fragments into buffer 0
        {
            uint32_t offA = (uint32_t)((cA ^ rx) << 4);
            uint32_t offB = (uint32_t)((cB ^ rx) << 4);
            LDSM_X4(ar[0][0][0], ar[0][0][1], ar[0][0][2], ar[0][0][3], stb + aroff[0] + offA);
            LDSM_X4(ar[0][1][0], ar[0][1][1], ar[0][1][2], ar[0][1][3], stb + aroff[1] + offA);
#pragma unroll
            for (int g = 0; g < 4; g++)
                LDSM_X4(br[0][g][0], br[0][g][1], br[0][g][2], br[0][g][3], stb + broff[g] + offB);
        }

#pragma unroll
        for (int kk = 0; kk < 4; kk++) {
            int cur = kk & 1, nxt = cur ^ 1;
            if (kk < 3) {
                uint32_t offA = (uint32_t)((((kk + 1) * 2 + cA) ^ rx) << 4);
                uint32_t offB = (uint32_t)((((kk + 1) * 2 + cB) ^ rx) << 4);
                LDSM_X4(ar[nxt][0][0], ar[nxt][0][1], ar[nxt][0][2], ar[nxt][0][3], stb + aroff[0] + offA);
                LDSM_X4(ar[nxt][1][0], ar[nxt][1][1], ar[nxt][1][2], ar[nxt][1][3], stb + aroff[1] + offA);
#pragma unroll
                for (int g = 0; g < 4; g++)
                    LDSM_X4(br[nxt][g][0], br[nxt][g][1], br[nxt][g][2], br[nxt][g][3], stb + broff[g] + offB);
            }
#pragma unroll
            for (int mf = 0; mf < 2; mf++)
#pragma unroll
                for (int nf = 0; nf < 8; nf++) {
                    int g = nf >> 1, h = (nf & 1) * 2;
                    MMA16816(acc[mf][nf], ar[cur][mf], br[cur][g][h], br[cur][g][h + 1]);
                }
        }
    }

    // ------------- fused epilogue -------------
    __syncthreads();
    // wait for the fx strip covering columns [n0, n0+128)
    if (t == 0) {
        while (atomicAdd(&g_flags[48 + blockIdx.x], 0) == 0) {}
        __threadfence();
    }
    __syncthreads();

    float* sred = reinterpret_cast<float*>(smem + SRED_OFF);
    float* fxs  = reinterpret_cast<float*>(smem + FXS_OFF);
    if (t < 128) fxs[t] = g_fx[n0 + t] + bfh[n0 + t];
    __syncthreads();

    int r0 = lane >> 2, q = lane & 3;
    float colsum[8][2];
#pragma unroll
    for (int nf = 0; nf < 8; nf++) { colsum[nf][0] = 0.f; colsum[nf][1] = 0.f; }

    const float* cbase = children_c + (size_t)(m0 + wm * 32) * HH + n0 + wn * 64;
#pragma unroll
    for (int mf = 0; mf < 2; mf++) {
        int rA = mf * 16 + r0;
        int rB = rA + 8;
#pragma unroll
        for (int nf = 0; nf < 8; nf++) {
            int cl = nf * 8 + q * 2;
            float2 ccA = *reinterpret_cast<const float2*>(cbase + (size_t)rA * HH + cl);
            float2 ccB = *reinterpret_cast<const float2*>(cbase + (size_t)rB * HH + cl);
            float fx0 = fxs[wn * 64 + cl];
            float fx1 = fxs[wn * 64 + cl + 1];
            const float* a = acc[mf][nf];
            float f00 = __fdividef(1.f, 1.f + __expf(-(fx0 + a[0])));
            float f01 = __fdividef(1.f, 1.f + __expf(-(fx1 + a[1])));
            float f10 = __fdividef(1.f, 1.f + __expf(-(fx0 + a[2])));
            float f11 = __fdividef(1.f, 1.f + __expf(-(fx1 + a[3])));
            colsum[nf][0] += f00 * ccA.x + f10 * ccB.x;
            colsum[nf][1] += f01 * ccA.y + f11 * ccB.y;
        }
    }
#pragma unroll
    for (int nf = 0; nf < 8; nf++) {
#pragma unroll
        for (int msk = 4; msk <= 16; msk <<= 1) {
            colsum[nf][0] += __shfl_xor_sync(0xFFFFFFFFu, colsum[nf][0], msk);
            colsum[nf][1] += __shfl_xor_sync(0xFFFFFFFFu, colsum[nf][1], msk);
        }
        if (lane < 4) {
            sred[wm * 128 + wn * 64 + nf * 8 + lane * 2 + 0] = colsum[nf][0];
            sred[wm * 128 + wn * 64 + nf * 8 + lane * 2 + 1] = colsum[nf][1];
        }
    }
    __syncthreads();
    if (t < 128) {
        float v = sred[t] + sred[128 + t] + sred[256 + t] + sred[384 + t];
        g_cpart[blockIdx.y][n0 + t] = v;
    }
    __threadfence();
    __syncthreads();
    if (t == 0) s_old = atomicAdd(&g_cnt[blockIdx.x], 1);
    __syncthreads();

    // ------------- final combine (last finisher per bx) -------------
    if (s_old == 31) {
        if (t == 0) {
            while (atomicAdd(&g_flags[blockIdx.x], 0) == 0) {}
            while (atomicAdd(&g_flags[16 + blockIdx.x], 0) == 0) {}
            while (atomicAdd(&g_flags[32 + blockIdx.x], 0) == 0) {}
            __threadfence();
        }
        __syncthreads();
        if (t < 128) {
            int n = n0 + t;
            float cr = 0.f;
#pragma unroll
            for (int r = 0; r < 32; r++) cr += g_cpart[r][n];
            float iv = g_iou[n];
            float ov = g_iou[HH + n];
            float uv = g_iou[2 * HH + n];
            float i_ = 1.f / (1.f + expf(-iv));
            float o_ = 1.f / (1.f + expf(-ov));
            float u_ = tanhf(uv);
            float c = i_ * u_ + cr;
            float h = o_ * tanhf(c);
            out[n] = o_;
            out[HH + n] = c;
            out[2 * HH + n] = h;
        }
    }
}

// ============================================================================
extern "C" void kernel_launch(void* const* d_in, const int* in_sizes, int n_in,
                              void* d_out, int out_size) {
    const float* input      = (const float*)d_in[0];
    const float* children_c = (const float*)d_in[1];
    const float* children_h = (const float*)d_in[2];
    const float* W_iou_x    = (const float*)d_in[3];
    const float* b_iou_x    = (const float*)d_in[4];
    const float* W_iou_h    = (const float*)d_in[5];
    const float* b_iou_h    = (const float*)d_in[6];
    const float* W_fx       = (const float*)d_in[7];
    const float* b_fx       = (const float*)d_in[8];
    const float* W_fh       = (const float*)d_in[9];
    const float* b_fh       = (const float*)d_in[10];
    float* out = (float*)d_out;

    cudaFuncSetAttribute(k_gemm, cudaFuncAttributeMaxDynamicSharedMemorySize, SMEM_TOTAL_G);

    k_prep<<<dim3(8, 256), 256>>>(children_h, W_fh);
    k_gemm<<<dim3(16, 32), 256, SMEM_TOTAL_G>>>(children_c, b_fh,
                                                input, W_iou_x, b_iou_x,
                                                W_iou_h, b_iou_h, W_fx, b_fx, out);
}

// round 12
// speedup vs baseline: 1.0287x; 1.0287x over previous
#include <cuda_runtime.h>
#include <cuda_fp16.h>
#include <cstdint>

// ---------------- problem constants ----------------
#define DD 2048
#define HH 2048
#define KK 4096

// ---------------- scratch (device globals; no allocation allowed) ----------
__device__ __half g_hA[(size_t)KK * HH];        // children_h in fp16 (16MB)
__device__ __half g_hB[(size_t)HH * HH];        // W_fh in fp16 (8MB)
__device__ float  g_hsum_part[128][HH];
__device__ float  g_iou[3 * HH];
__device__ float  g_fx[HH];
__device__ float  g_cpart[32][HH];              // per-M-tile partial c sums
__device__ int    g_flags[64];                  // gemv strip ready flags
__device__ int    g_cnt[16];                    // per-bx completion counters

// ---------------- PTX helpers ----------------
__device__ __forceinline__ uint32_t smem_u32(const void* p) {
    uint32_t a;
    asm("{ .reg .u64 t; cvta.to.shared.u64 t, %1; cvt.u32.u64 %0, t; }" : "=r"(a) : "l"(p));
    return a;
}

#define CP_ASYNC16(dst, src) \
    asm volatile("cp.async.cg.shared.global [%0], [%1], 16;" :: "r"(dst), "l"(src))
#define CP_COMMIT() asm volatile("cp.async.commit_group;")
#define CP_WAIT(n)  asm volatile("cp.async.wait_group %0;" :: "n"(n))

#define LDSM_X4(r0, r1, r2, r3, addr) \
    asm volatile("ldmatrix.sync.aligned.m8n8.x4.shared.b16 {%0,%1,%2,%3}, [%4];" \
        : "=r"(r0), "=r"(r1), "=r"(r2), "=r"(r3) : "r"(addr))

#define MMA16816(d, a, b0, b1) \
    asm volatile("mma.sync.aligned.m16n8k16.row.col.f32.f16.f16.f32 " \
        "{%0,%1,%2,%3},{%4,%5,%6,%7},{%8,%9},{%0,%1,%2,%3};" \
        : "+f"((d)[0]), "+f"((d)[1]), "+f"((d)[2]), "+f"((d)[3]) \
        : "r"((a)[0]), "r"((a)[1]), "r"((a)[2]), "r"((a)[3]), "r"(b0), "r"(b1))

// ============================================================================
// Kernel 1: merged prep, 2048 blocks.
//  by < 128 : column-sum partials of children_h (32-row strips) + fp16 convert
//  by >= 128: W_fh fp32->fp16 convert (1024 blocks, 4 float4/thread)
// grid (8, 256), 256 threads
// ============================================================================
__global__ __launch_bounds__(256) void k_prep(const float* __restrict__ ch,
                                              const float* __restrict__ W) {
    int t = threadIdx.x;
    if (blockIdx.y < 128) {
        int cs = blockIdx.x, rs = blockIdx.y;
        int tx = t & 63, ty = t >> 6;
        int col = cs * 256 + tx * 4;
        int row0 = rs * 32 + ty * 8;
        float4 acc = make_float4(0.f, 0.f, 0.f, 0.f);
#pragma unroll
        for (int r = 0; r < 8; r++) {
            size_t off = (size_t)(row0 + r) * HH + col;
            float4 v = *reinterpret_cast<const float4*>(ch + off);
            acc.x += v.x; acc.y += v.y; acc.z += v.z; acc.w += v.w;
            union { __half2 h2[2]; uint2 u; } cv;
            cv.h2[0] = __floats2half2_rn(v.x, v.y);
            cv.h2[1] = __floats2half2_rn(v.z, v.w);
            *reinterpret_cast<uint2*>(g_hA + off) = cv.u;
        }
        __shared__ float sp[4][256];
        sp[ty][tx * 4 + 0] = acc.x;
        sp[ty][tx * 4 + 1] = acc.y;
        sp[ty][tx * 4 + 2] = acc.z;
        sp[ty][tx * 4 + 3] = acc.w;
        __syncthreads();
        float s = sp[0][t] + sp[1][t] + sp[2][t] + sp[3][t];
        g_hsum_part[rs][cs * 256 + t] = s;
    } else {
        int pb = blockIdx.x + 8 * (blockIdx.y - 128);    // 0..1023
        if (pb == 0 && t < 80) {
            if (t < 64) g_flags[t] = 0;
            else        g_cnt[t - 64] = 0;
        }
#pragma unroll
        for (int k = 0; k < 4; k++) {
            int i = pb * 1024 + k * 256 + t;
            float4 v = reinterpret_cast<const float4*>(W)[i];
            union { __half2 h2[2]; uint2 u; } cv;
            cv.h2[0] = __floats2half2_rn(v.x, v.y);
            cv.h2[1] = __floats2half2_rn(v.z, v.w);
            reinterpret_cast<uint2*>(g_hB)[i] = cv.u;
        }
    }
}

// ============================================================================
// Kernel 2: HMMA fp16 GEMM fh = children_h @ W_fh^T fused with
//   c_partial[n] += sum_m sigmoid(fx+b_fh+fh[m][n]) * children_c[m][n]
// R10 config (BM=128, BN=128, BK=64 XOR-swizzled, warp 32x64, 2 CTAs/SM,
// NST=3) + B-FRAGMENT DOUBLE-BUFFERING ONLY (fits the 128-reg cap):
// per kk, B(kk+1) ldsm issues into the alternate buffer while kk's MMAs
// drain, keeping the smem crossbar busy under the tensor phase (breaks the
// WAR-induced LDSM/MMA phase-lock measured in R10).
// Grid (16 nT, 32 mT). First 64 CTAs (by<4) run the embedded GEMV producer
// prologue; last finisher per bx (counter==31) runs the final combine.
// ============================================================================
#define STB 32768                    // stage bytes: A 16KB + B 16KB
#define NST 3
#define SRED_OFF (NST * STB)         // 98304
#define FXS_OFF  (SRED_OFF + 4 * 128 * 4)
#define SMEM_TOTAL_G (FXS_OFF + 128 * 4)

__global__ __launch_bounds__(256, 2) void k_gemm(const float* __restrict__ children_c,
                                                 const float* __restrict__ bfh,
                                                 const float* __restrict__ input,
                                                 const float* __restrict__ Wix,
                                                 const float* __restrict__ bix,
                                                 const float* __restrict__ Wih,
                                                 const float* __restrict__ bih,
                                                 const float* __restrict__ Wfx,
                                                 const float* __restrict__ bfx,
                                                 float* __restrict__ out) {
    extern __shared__ __align__(1024) char smem[];
    __shared__ int s_old;
    uint32_t smb = smem_u32(smem);
    int t = threadIdx.x;
    int lane = t & 31, wid = t >> 5;
    int wm = wid & 3, wn = wid >> 2;
    int n0 = blockIdx.x * 128;
    int m0 = blockIdx.y * 128;

    // ------------- embedded GEMV producer prologue -------------
    if (blockIdx.y < 4) {
        int p = blockIdx.x + 16 * blockIdx.y;            // strip 0..63
        float* s_vec = reinterpret_cast<float*>(smem);   // input  [0,2048)
        float* s_hv  = reinterpret_cast<float*>(smem) + 2048;
        for (int i = t; i < 512; i += 256)
            reinterpret_cast<float4*>(s_vec)[i] = reinterpret_cast<const float4*>(input)[i];
        bool is_iou = (p < 48);
        if (is_iou) {
            for (int c = t; c < 2048; c += 256) {
                float s = 0.f;
#pragma unroll
                for (int r = 0; r < 128; r++) s += g_hsum_part[r][c];
                s_hv[c] = s;
            }
        }
        __syncthreads();
        int rbase = p * 128 + wid * 16;
        const float4* xi = reinterpret_cast<const float4*>(s_vec);
        const float4* xh = reinterpret_cast<const float4*>(s_hv);
#pragma unroll 1
        for (int rr = 0; rr < 16; rr += 2) {
            int R = rbase + rr;
            float acc0 = 0.f, acc1 = 0.f;
            if (is_iou) {
                const float4* w1a = reinterpret_cast<const float4*>(Wix + (size_t)R * DD);
                const float4* w1b = reinterpret_cast<const float4*>(Wix + (size_t)(R + 1) * DD);
                const float4* w2a = reinterpret_cast<const float4*>(Wih + (size_t)R * HH);
                const float4* w2b = reinterpret_cast<const float4*>(Wih + (size_t)(R + 1) * HH);
#pragma unroll
                for (int q = 0; q < 16; q++) {
                    float4 b = xi[q * 32 + lane];
                    float4 a0 = w1a[q * 32 + lane];
                    float4 a1 = w1b[q * 32 + lane];
                    acc0 += a0.x * b.x + a0.y * b.y + a0.z * b.z + a0.w * b.w;
                    acc1 += a1.x * b.x + a1.y * b.y + a1.z * b.z + a1.w * b.w;
                }
#pragma unroll
                for (int q = 0; q < 16; q++) {
                    float4 b = xh[q * 32 + lane];
                    float4 a0 = w2a[q * 32 + lane];
                    float4 a1 = w2b[q * 32 + lane];
                    acc0 += a0.x * b.x + a0.y * b.y + a0.z * b.z + a0.w * b.w;
                    acc1 += a1.x * b.x + a1.y * b.y + a1.z * b.z + a1.w * b.w;
                }
            } else {
                int j = R - 3 * HH;
                const float4* wa = reinterpret_cast<const float4*>(Wfx + (size_t)j * DD);
                const float4* wb = reinterpret_cast<const float4*>(Wfx + (size_t)(j + 1) * DD);
#pragma unroll
                for (int q = 0; q < 16; q++) {
                    float4 b = xi[q * 32 + lane];
                    float4 a0 = wa[q * 32 + lane];
                    float4 a1 = wb[q * 32 + lane];
                    acc0 += a0.x * b.x + a0.y * b.y + a0.z * b.z + a0.w * b.w;
                    acc1 += a1.x * b.x + a1.y * b.y + a1.z * b.z + a1.w * b.w;
                }
            }
#pragma unroll
            for (int off = 16; off; off >>= 1) {
                acc0 += __shfl_xor_sync(0xFFFFFFFFu, acc0, off);
                acc1 += __shfl_xor_sync(0xFFFFFFFFu, acc1, off);
            }
            if (lane == 0) {
                if (is_iou) {
                    g_iou[R]     = acc0 + bix[R] + bih[R];
                    g_iou[R + 1] = acc1 + bix[R + 1] + bih[R + 1];
                } else {
                    int j = R - 3 * HH;
                    g_fx[j]     = acc0 + bfx[j];
                    g_fx[j + 1] = acc1 + bfx[j + 1];
                }
            }
        }
        __threadfence();
        __syncthreads();
        if (t == 0) atomicExch(&g_flags[p], 1);
        __syncthreads();      // smem about to be reused by pipeline
    }

    // ------------- MMA mainloop (BK=64, swizzled 128B rows) -------------
    int rx = lane & 7;                 // row & 7 for all fragment rows
    int cA = lane >> 4;                // A: which 16B half of k16
    int cB = (lane >> 3) & 1;          // B: which 16B half of k16

    uint32_t aroff[2], broff[4];
#pragma unroll
    for (int mf = 0; mf < 2; mf++)
        aroff[mf] = (uint32_t)((wm * 32 + mf * 16 + (lane & 15)) << 7);
#pragma unroll
    for (int g = 0; g < 4; g++)
        broff[g] = (uint32_t)(16384 + ((wn * 64 + g * 16 + ((lane >> 4) << 3) + (lane & 7)) << 7));

    auto issue_load = [&](int ci, int s) {
        uint32_t st = smb + s * STB;
#pragma unroll
        for (int j = 0; j < 4; j++) {
            int idx = j * 256 + t;
            int r = idx >> 3, c = idx & 7;
            uint32_t off = (uint32_t)(r << 7) + (uint32_t)(((c ^ (r & 7))) << 4);
            const __half* srcA = g_hA + (size_t)(m0 + r) * HH + ci * 64 + c * 8;
            CP_ASYNC16(st + off, __cvta_generic_to_global(srcA));
            const __half* srcB = g_hB + (size_t)(n0 + r) * HH + ci * 64 + c * 8;
            CP_ASYNC16(st + 16384 + off, __cvta_generic_to_global(srcB));
        }
        CP_COMMIT();
    };

    float acc[2][8][4];
#pragma unroll
    for (int mf = 0; mf < 2; mf++)
#pragma unroll
        for (int nf = 0; nf < 8; nf++)
#pragma unroll
            for (int q = 0; q < 4; q++) acc[mf][nf][q] = 0.f;

    issue_load(0, 0);
    issue_load(1, 1);

    // fragment buffers: A single (8 regs), B double (32 regs)
    uint32_t ar[2][4];
    uint32_t br[2][4][4];

    int s = 0;
    for (int ci = 0; ci < 32; ci++) {
        CP_WAIT(1);
        __syncthreads();
        if (ci + 2 < 32) {
            int s2 = s + 2; if (s2 >= 3) s2 -= 3;
            issue_load(ci + 2, s2);
        } else CP_COMMIT();

        uint32_t stb = smb + (uint32_t)s * STB;

        // preload B(kk=0) into br[0]
        {
            uint32_t offB0 = (uint32_t)((cB ^ rx) << 4);
#pragma unroll
            for (int g = 0; g < 4; g++)
                LDSM_X4(br[0][g][0], br[0][g][1], br[0][g][2], br[0][g][3],
                        stb + broff[g] + offB0);
        }

#pragma unroll
        for (int kk = 0; kk < 4; kk++) {
            int cur = kk & 1, nxt = cur ^ 1;
            // A(kk) into the single buffer (WAR on kk-1 MMAs clears at issue)
            {
                uint32_t offA = (uint32_t)(((kk * 2 + cA) ^ rx) << 4);
                LDSM_X4(ar[0][0], ar[0][1], ar[0][2], ar[0][3], stb + aroff[0] + offA);
                LDSM_X4(ar[1][0], ar[1][1], ar[1][2], ar[1][3], stb + aroff[1] + offA);
            }
            // B(kk+1) into the alternate buffer -> overlaps kk's MMA stream
            if (kk < 3) {
                uint32_t offB = (uint32_t)((((kk + 1) * 2 + cB) ^ rx) << 4);
#pragma unroll
                for (int g = 0; g < 4; g++)
                    LDSM_X4(br[nxt][g][0], br[nxt][g][1], br[nxt][g][2], br[nxt][g][3],
                            stb + broff[g] + offB);
            }
#pragma unroll
            for (int mf = 0; mf < 2; mf++)
#pragma unroll
                for (int nf = 0; nf < 8; nf++) {
                    int g = nf >> 1, h = (nf & 1) * 2;
                    MMA16816(acc[mf][nf], ar[mf], br[cur][g][h], br[cur][g][h + 1]);
                }
        }
        if (++s >= 3) s -= 3;
    }

    // ------------- fused epilogue -------------
    __syncthreads();
    // wait for the fx strip covering columns [n0, n0+128)
    if (t == 0) {
        while (atomicAdd(&g_flags[48 + blockIdx.x], 0) == 0) {}
        __threadfence();
    }
    __syncthreads();

    float* sred = reinterpret_cast<float*>(smem + SRED_OFF);
    float* fxs  = reinterpret_cast<float*>(smem + FXS_OFF);
    if (t < 128) fxs[t] = g_fx[n0 + t] + bfh[n0 + t];
    __syncthreads();

    int r0 = lane >> 2, q = lane & 3;
    float colsum[8][2];
#pragma unroll
    for (int nf = 0; nf < 8; nf++) { colsum[nf][0] = 0.f; colsum[nf][1] = 0.f; }

    const float* cbase = children_c + (size_t)(m0 + wm * 32) * HH + n0 + wn * 64;
#pragma unroll
    for (int mf = 0; mf < 2; mf++) {
        int rA = mf * 16 + r0;
        int rB = rA + 8;
#pragma unroll
        for (int nf = 0; nf < 8; nf++) {
            int cl = nf * 8 + q * 2;
            float2 ccA = *reinterpret_cast<const float2*>(cbase + (size_t)rA * HH + cl);
            float2 ccB = *reinterpret_cast<const float2*>(cbase + (size_t)rB * HH + cl);
            float fx0 = fxs[wn * 64 + cl];
            float fx1 = fxs[wn * 64 + cl + 1];
            const float* a = acc[mf][nf];
            float f00 = __fdividef(1.f, 1.f + __expf(-(fx0 + a[0])));
            float f01 = __fdividef(1.f, 1.f + __expf(-(fx1 + a[1])));
            float f10 = __fdividef(1.f, 1.f + __expf(-(fx0 + a[2])));
            float f11 = __fdividef(1.f, 1.f + __expf(-(fx1 + a[3])));
            colsum[nf][0] += f00 * ccA.x + f10 * ccB.x;
            colsum[nf][1] += f01 * ccA.y + f11 * ccB.y;
        }
    }
#pragma unroll
    for (int nf = 0; nf < 8; nf++) {
#pragma unroll
        for (int msk = 4; msk <= 16; msk <<= 1) {
            colsum[nf][0] += __shfl_xor_sync(0xFFFFFFFFu, colsum[nf][0], msk);
            colsum[nf][1] += __shfl_xor_sync(0xFFFFFFFFu, colsum[nf][1], msk);
        }
        if (lane < 4) {
            sred[wm * 128 + wn * 64 + nf * 8 + lane * 2 + 0] = colsum[nf][0];
            sred[wm * 128 + wn * 64 + nf * 8 + lane * 2 + 1] = colsum[nf][1];
        }
    }
    __syncthreads();
    if (t < 128) {
        float v = sred[t] + sred[128 + t] + sred[256 + t] + sred[384 + t];
        g_cpart[blockIdx.y][n0 + t] = v;
    }
    __threadfence();
    __syncthreads();
    if (t == 0) s_old = atomicAdd(&g_cnt[blockIdx.x], 1);
    __syncthreads();

    // ------------- final combine (last finisher per bx) -------------
    if (s_old == 31) {
        if (t == 0) {
            while (atomicAdd(&g_flags[blockIdx.x], 0) == 0) {}
            while (atomicAdd(&g_flags[16 + blockIdx.x], 0) == 0) {}
            while (atomicAdd(&g_flags[32 + blockIdx.x], 0) == 0) {}
            __threadfence();
        }
        __syncthreads();
        if (t < 128) {
            int n = n0 + t;
            float cr = 0.f;
#pragma unroll
            for (int r = 0; r < 32; r++) cr += g_cpart[r][n];
            float iv = g_iou[n];
            float ov = g_iou[HH + n];
            float uv = g_iou[2 * HH + n];
            float i_ = 1.f / (1.f + expf(-iv));
            float o_ = 1.f / (1.f + expf(-ov));
            float u_ = tanhf(uv);
            float c = i_ * u_ + cr;
            float h = o_ * tanhf(c);
            out[n] = o_;
            out[HH + n] = c;
            out[2 * HH + n] = h;
        }
    }
}

// ============================================================================
extern "C" void kernel_launch(void* const* d_in, const int* in_sizes, int n_in,
                              void* d_out, int out_size) {
    const float* input      = (const float*)d_in[0];
    const float* children_c = (const float*)d_in[1];
    const float* children_h = (const float*)d_in[2];
    const float* W_iou_x    = (const float*)d_in[3];
    const float* b_iou_x    = (const float*)d_in[4];
    const float* W_iou_h    = (const float*)d_in[5];
    const float* b_iou_h    = (const float*)d_in[6];
    const float* W_fx       = (const float*)d_in[7];
    const float* b_fx       = (const float*)d_in[8];
    const float* W_fh       = (const float*)d_in[9];
    const float* b_fh       = (const float*)d_in[10];
    float* out = (float*)d_out;

    cudaFuncSetAttribute(k_gemm, cudaFuncAttributeMaxDynamicSharedMemorySize, SMEM_TOTAL_G);

    k_prep<<<dim3(8, 256), 256>>>(children_h, W_fh);
    k_gemm<<<dim3(16, 32), 256, SMEM_TOTAL_G>>>(children_c, b_fh,
                                                input, W_iou_x, b_iou_x,
                                                W_iou_h, b_iou_h, W_fx, b_fx, out);
}

// round 13
// speedup vs baseline: 1.0925x; 1.0620x over previous
#include <cuda_runtime.h>
#include <cuda_fp16.h>
#include <cstdint>

// ---------------- problem constants ----------------
#define DD 2048
#define HH 2048
#define KK 4096

// ---------------- scratch (device globals; no allocation allowed) ----------
__device__ __half g_hA[(size_t)KK * HH];        // children_h in fp16 (16MB)
__device__ __half g_hB[(size_t)HH * HH];        // W_fh in fp16 (8MB)
__device__ float  g_hsum_part[128][HH];
__device__ float  g_iou[3 * HH];
__device__ float  g_fx[HH];
__device__ float  g_cpart[32][HH];              // per-M-tile partial c sums
__device__ int    g_flags[64];                  // gemv strip ready flags
__device__ int    g_cnt[16];                    // per-bx completion counters

// ---------------- PTX helpers ----------------
__device__ __forceinline__ uint32_t smem_u32(const void* p) {
    uint32_t a;
    asm("{ .reg .u64 t; cvta.to.shared.u64 t, %1; cvt.u32.u64 %0, t; }" : "=r"(a) : "l"(p));
    return a;
}

#define CP_ASYNC16(dst, src) \
    asm volatile("cp.async.cg.shared.global [%0], [%1], 16;" :: "r"(dst), "l"(src))
#define CP_COMMIT() asm volatile("cp.async.commit_group;")
#define CP_WAIT(n)  asm volatile("cp.async.wait_group %0;" :: "n"(n))

#define LDSM_X4(r0, r1, r2, r3, addr) \
    asm volatile("ldmatrix.sync.aligned.m8n8.x4.shared.b16 {%0,%1,%2,%3}, [%4];" \
        : "=r"(r0), "=r"(r1), "=r"(r2), "=r"(r3) : "r"(addr))

#define MMA16816(d, a, b0, b1) \
    asm volatile("mma.sync.aligned.m16n8k16.row.col.f32.f16.f16.f32 " \
        "{%0,%1,%2,%3},{%4,%5,%6,%7},{%8,%9},{%0,%1,%2,%3};" \
        : "+f"((d)[0]), "+f"((d)[1]), "+f"((d)[2]), "+f"((d)[3]) \
        : "r"((a)[0]), "r"((a)[1]), "r"((a)[2]), "r"((a)[3]), "r"(b0), "r"(b1))

// ============================================================================
// Kernel 1: merged prep, 2048 blocks, MLP-4 batched loads.
//  by < 128 : column-sum partials of children_h (32-row strips) + fp16 convert
//  by >= 128: W_fh fp32->fp16 convert (1024 blocks, 4 float4/thread, batched)
// grid (8, 256), 256 threads
// ============================================================================
__global__ __launch_bounds__(256) void k_prep(const float* __restrict__ ch,
                                              const float* __restrict__ W) {
    int t = threadIdx.x;
    if (blockIdx.y < 128) {
        int cs = blockIdx.x, rs = blockIdx.y;
        int tx = t & 63, ty = t >> 6;
        int col = cs * 256 + tx * 4;
        int row0 = rs * 32 + ty * 8;
        float4 acc = make_float4(0.f, 0.f, 0.f, 0.f);
        // two 4-deep load batches (front-batched LDG -> MLP 4)
#pragma unroll
        for (int half = 0; half < 2; half++) {
            float4 v[4];
#pragma unroll
            for (int r = 0; r < 4; r++) {
                size_t off = (size_t)(row0 + half * 4 + r) * HH + col;
                v[r] = *reinterpret_cast<const float4*>(ch + off);
            }
#pragma unroll
            for (int r = 0; r < 4; r++) {
                size_t off = (size_t)(row0 + half * 4 + r) * HH + col;
                acc.x += v[r].x; acc.y += v[r].y; acc.z += v[r].z; acc.w += v[r].w;
                union { __half2 h2[2]; uint2 u; } cv;
                cv.h2[0] = __floats2half2_rn(v[r].x, v[r].y);
                cv.h2[1] = __floats2half2_rn(v[r].z, v[r].w);
                *reinterpret_cast<uint2*>(g_hA + off) = cv.u;
            }
        }
        __shared__ float sp[4][256];
        sp[ty][tx * 4 + 0] = acc.x;
        sp[ty][tx * 4 + 1] = acc.y;
        sp[ty][tx * 4 + 2] = acc.z;
        sp[ty][tx * 4 + 3] = acc.w;
        __syncthreads();
        float s = sp[0][t] + sp[1][t] + sp[2][t] + sp[3][t];
        g_hsum_part[rs][cs * 256 + t] = s;
    } else {
        int pb = blockIdx.x + 8 * (blockIdx.y - 128);    // 0..1023
        if (pb == 0 && t < 80) {
            if (t < 64) g_flags[t] = 0;
            else        g_cnt[t - 64] = 0;
        }
        float4 v[4];
#pragma unroll
        for (int k = 0; k < 4; k++)
            v[k] = reinterpret_cast<const float4*>(W)[pb * 1024 + k * 256 + t];
#pragma unroll
        for (int k = 0; k < 4; k++) {
            union { __half2 h2[2]; uint2 u; } cv;
            cv.h2[0] = __floats2half2_rn(v[k].x, v[k].y);
            cv.h2[1] = __floats2half2_rn(v[k].z, v[k].w);
            reinterpret_cast<uint2*>(g_hB)[pb * 1024 + k * 256 + t] = cv.u;
        }
    }
}

// ============================================================================
// Kernel 2: HMMA fp16 GEMM fh = children_h @ W_fh^T fused with
//   c_partial[n] += sum_m sigmoid(fx+b_fh+fh[m][n]) * children_c[m][n]
// R10 config byte-exact: BM=128, BN=128, BK=64 XOR-swizzled 128B rows,
// warp tile 32x64 (8 warps 4m x 2n), 2 CTAs/SM, NST=3, single-buffered
// fragments (measured at ~94% of the mma.sync fp32-acc tensor roofline).
// Grid (16 nT, 32 mT). First 64 CTAs (by<4) run the embedded GEMV producer
// prologue; last finisher per bx (counter==31) runs the final combine.
// ============================================================================
#define STB 32768                    // stage bytes: A 16KB + B 16KB
#define NST 3
#define SRED_OFF (NST * STB)         // 98304
#define FXS_OFF  (SRED_OFF + 4 * 128 * 4)
#define SMEM_TOTAL_G (FXS_OFF + 128 * 4)

__global__ __launch_bounds__(256, 2) void k_gemm(const float* __restrict__ children_c,
                                                 const float* __restrict__ bfh,
                                                 const float* __restrict__ input,
                                                 const float* __restrict__ Wix,
                                                 const float* __restrict__ bix,
                                                 const float* __restrict__ Wih,
                                                 const float* __restrict__ bih,
                                                 const float* __restrict__ Wfx,
                                                 const float* __restrict__ bfx,
                                                 float* __restrict__ out) {
    extern __shared__ __align__(1024) char smem[];
    __shared__ int s_old;
    uint32_t smb = smem_u32(smem);
    int t = threadIdx.x;
    int lane = t & 31, wid = t >> 5;
    int wm = wid & 3, wn = wid >> 2;
    int n0 = blockIdx.x * 128;
    int m0 = blockIdx.y * 128;

    // ------------- embedded GEMV producer prologue -------------
    if (blockIdx.y < 4) {
        int p = blockIdx.x + 16 * blockIdx.y;            // strip 0..63
        float* s_vec = reinterpret_cast<float*>(smem);   // input  [0,2048)
        float* s_hv  = reinterpret_cast<float*>(smem) + 2048;
        for (int i = t; i < 512; i += 256)
            reinterpret_cast<float4*>(s_vec)[i] = reinterpret_cast<const float4*>(input)[i];
        bool is_iou = (p < 48);
        if (is_iou) {
            for (int c = t; c < 2048; c += 256) {
                float s = 0.f;
#pragma unroll
                for (int r = 0; r < 128; r++) s += g_hsum_part[r][c];
                s_hv[c] = s;
            }
        }
        __syncthreads();
        int rbase = p * 128 + wid * 16;
        const float4* xi = reinterpret_cast<const float4*>(s_vec);
        const float4* xh = reinterpret_cast<const float4*>(s_hv);
#pragma unroll 1
        for (int rr = 0; rr < 16; rr += 2) {
            int R = rbase + rr;
            float acc0 = 0.f, acc1 = 0.f;
            if (is_iou) {
                const float4* w1a = reinterpret_cast<const float4*>(Wix + (size_t)R * DD);
                const float4* w1b = reinterpret_cast<const float4*>(Wix + (size_t)(R + 1) * DD);
                const float4* w2a = reinterpret_cast<const float4*>(Wih + (size_t)R * HH);
                const float4* w2b = reinterpret_cast<const float4*>(Wih + (size_t)(R + 1) * HH);
#pragma unroll
                for (int q = 0; q < 16; q++) {
                    float4 b = xi[q * 32 + lane];
                    float4 a0 = w1a[q * 32 + lane];
                    float4 a1 = w1b[q * 32 + lane];
                    acc0 += a0.x * b.x + a0.y * b.y + a0.z * b.z + a0.w * b.w;
                    acc1 += a1.x * b.x + a1.y * b.y + a1.z * b.z + a1.w * b.w;
                }
#pragma unroll
                for (int q = 0; q < 16; q++) {
                    float4 b = xh[q * 32 + lane];
                    float4 a0 = w2a[q * 32 + lane];
                    float4 a1 = w2b[q * 32 + lane];
                    acc0 += a0.x * b.x + a0.y * b.y + a0.z * b.z + a0.w * b.w;
                    acc1 += a1.x * b.x + a1.y * b.y + a1.z * b.z + a1.w * b.w;
                }
            } else {
                int j = R - 3 * HH;
                const float4* wa = reinterpret_cast<const float4*>(Wfx + (size_t)j * DD);
                const float4* wb = reinterpret_cast<const float4*>(Wfx + (size_t)(j + 1) * DD);
#pragma unroll
                for (int q = 0; q < 16; q++) {
                    float4 b = xi[q * 32 + lane];
                    float4 a0 = wa[q * 32 + lane];
                    float4 a1 = wb[q * 32 + lane];
                    acc0 += a0.x * b.x + a0.y * b.y + a0.z * b.z + a0.w * b.w;
                    acc1 += a1.x * b.x + a1.y * b.y + a1.z * b.z + a1.w * b.w;
                }
            }
#pragma unroll
            for (int off = 16; off; off >>= 1) {
                acc0 += __shfl_xor_sync(0xFFFFFFFFu, acc0, off);
                acc1 += __shfl_xor_sync(0xFFFFFFFFu, acc1, off);
            }
            if (lane == 0) {
                if (is_iou) {
                    g_iou[R]     = acc0 + bix[R] + bih[R];
                    g_iou[R + 1] = acc1 + bix[R + 1] + bih[R + 1];
                } else {
                    int j = R - 3 * HH;
                    g_fx[j]     = acc0 + bfx[j];
                    g_fx[j + 1] = acc1 + bfx[j + 1];
                }
            }
        }
        __threadfence();
        __syncthreads();
        if (t == 0) atomicExch(&g_flags[p], 1);
        __syncthreads();      // smem about to be reused by pipeline
    }

    // ------------- MMA mainloop (BK=64, swizzled 128B rows) -------------
    int rx = lane & 7;                 // row & 7 for all fragment rows
    int cA = lane >> 4;                // A: which 16B half of k16
    int cB = (lane >> 3) & 1;          // B: which 16B half of k16

    uint32_t aroff[2], broff[4];
#pragma unroll
    for (int mf = 0; mf < 2; mf++)
        aroff[mf] = (uint32_t)((wm * 32 + mf * 16 + (lane & 15)) << 7);
#pragma unroll
    for (int g = 0; g < 4; g++)
        broff[g] = (uint32_t)(16384 + ((wn * 64 + g * 16 + ((lane >> 4) << 3) + (lane & 7)) << 7));

    auto issue_load = [&](int ci, int s) {
        uint32_t st = smb + s * STB;
#pragma unroll
        for (int j = 0; j < 4; j++) {
            int idx = j * 256 + t;
            int r = idx >> 3, c = idx & 7;
            uint32_t off = (uint32_t)(r << 7) + (uint32_t)(((c ^ (r & 7))) << 4);
            const __half* srcA = g_hA + (size_t)(m0 + r) * HH + ci * 64 + c * 8;
            CP_ASYNC16(st + off, __cvta_generic_to_global(srcA));
            const __half* srcB = g_hB + (size_t)(n0 + r) * HH + ci * 64 + c * 8;
            CP_ASYNC16(st + 16384 + off, __cvta_generic_to_global(srcB));
        }
        CP_COMMIT();
    };

    float acc[2][8][4];
#pragma unroll
    for (int mf = 0; mf < 2; mf++)
#pragma unroll
        for (int nf = 0; nf < 8; nf++)
#pragma unroll
            for (int q = 0; q < 4; q++) acc[mf][nf][q] = 0.f;

    issue_load(0, 0);
    issue_load(1, 1);

    int s = 0;
    for (int ci = 0; ci < 32; ci++) {
        CP_WAIT(1);
        __syncthreads();
        if (ci + 2 < 32) {
            int s2 = s + 2; if (s2 >= 3) s2 -= 3;
            issue_load(ci + 2, s2);
        } else CP_COMMIT();

        uint32_t stb = smb + (uint32_t)s * STB;
#pragma unroll
        for (int kk = 0; kk < 4; kk++) {
            uint32_t offA = (uint32_t)(((kk * 2 + cA) ^ rx) << 4);
            uint32_t offB = (uint32_t)(((kk * 2 + cB) ^ rx) << 4);
            uint32_t ar[2][4];
            LDSM_X4(ar[0][0], ar[0][1], ar[0][2], ar[0][3], stb + aroff[0] + offA);
            LDSM_X4(ar[1][0], ar[1][1], ar[1][2], ar[1][3], stb + aroff[1] + offA);
            uint32_t br[4][4];
#pragma unroll
            for (int g = 0; g < 4; g++)
                LDSM_X4(br[g][0], br[g][1], br[g][2], br[g][3], stb + broff[g] + offB);
#pragma unroll
            for (int mf = 0; mf < 2; mf++)
#pragma unroll
                for (int nf = 0; nf < 8; nf++) {
                    int g = nf >> 1, h = (nf & 1) * 2;
                    MMA16816(acc[mf][nf], ar[mf], br[g][h], br[g][h + 1]);
                }
        }
        if (++s >= 3) s -= 3;
    }

    // ------------- fused epilogue -------------
    __syncthreads();
    // wait for the fx strip covering columns [n0, n0+128)
    if (t == 0) {
        while (atomicAdd(&g_flags[48 + blockIdx.x], 0) == 0) {}
        __threadfence();
    }
    __syncthreads();

    float* sred = reinterpret_cast<float*>(smem + SRED_OFF);
    float* fxs  = reinterpret_cast<float*>(smem + FXS_OFF);
    if (t < 128) fxs[t] = g_fx[n0 + t] + bfh[n0 + t];
    __syncthreads();

    int r0 = lane >> 2, q = lane & 3;
    float colsum[8][2];
#pragma unroll
    for (int nf = 0; nf < 8; nf++) { colsum[nf][0] = 0.f; colsum[nf][1] = 0.f; }

    const float* cbase = children_c + (size_t)(m0 + wm * 32) * HH + n0 + wn * 64;
#pragma unroll
    for (int mf = 0; mf < 2; mf++) {
        int rA = mf * 16 + r0;
        int rB = rA + 8;
#pragma unroll
        for (int nf = 0; nf < 8; nf++) {
            int cl = nf * 8 + q * 2;
            float2 ccA = *reinterpret_cast<const float2*>(cbase + (size_t)rA * HH + cl);
            float2 ccB = *reinterpret_cast<const float2*>(cbase + (size_t)rB * HH + cl);
            float fx0 = fxs[wn * 64 + cl];
            float fx1 = fxs[wn * 64 + cl + 1];
            const float* a = acc[mf][nf];
            float f00 = __fdividef(1.f, 1.f + __expf(-(fx0 + a[0])));
            float f01 = __fdividef(1.f, 1.f + __expf(-(fx1 + a[1])));
            float f10 = __fdividef(1.f, 1.f + __expf(-(fx0 + a[2])));
            float f11 = __fdividef(1.f, 1.f + __expf(-(fx1 + a[3])));
            colsum[nf][0] += f00 * ccA.x + f10 * ccB.x;
            colsum[nf][1] += f01 * ccA.y + f11 * ccB.y;
        }
    }
#pragma unroll
    for (int nf = 0; nf < 8; nf++) {
#pragma unroll
        for (int msk = 4; msk <= 16; msk <<= 1) {
            colsum[nf][0] += __shfl_xor_sync(0xFFFFFFFFu, colsum[nf][0], msk);
            colsum[nf][1] += __shfl_xor_sync(0xFFFFFFFFu, colsum[nf][1], msk);
        }
        if (lane < 4) {
            sred[wm * 128 + wn * 64 + nf * 8 + lane * 2 + 0] = colsum[nf][0];
            sred[wm * 128 + wn * 64 + nf * 8 + lane * 2 + 1] = colsum[nf][1];
        }
    }
    __syncthreads();
    if (t < 128) {
        float v = sred[t] + sred[128 + t] + sred[256 + t] + sred[384 + t];
        g_cpart[blockIdx.y][n0 + t] = v;
    }
    __threadfence();
    __syncthreads();
    if (t == 0) s_old = atomicAdd(&g_cnt[blockIdx.x], 1);
    __syncthreads();

    // ------------- final combine (last finisher per bx) -------------
    if (s_old == 31) {
        if (t == 0) {
            while (atomicAdd(&g_flags[blockIdx.x], 0) == 0) {}
            while (atomicAdd(&g_flags[16 + blockIdx.x], 0) == 0) {}
            while (atomicAdd(&g_flags[32 + blockIdx.x], 0) == 0) {}
            __threadfence();
        }
        __syncthreads();
        if (t < 128) {
            int n = n0 + t;
            float cr = 0.f;
#pragma unroll
            for (int r = 0; r < 32; r++) cr += g_cpart[r][n];
            float iv = g_iou[n];
            float ov = g_iou[HH + n];
            float uv = g_iou[2 * HH + n];
            float i_ = 1.f / (1.f + expf(-iv));
            float o_ = 1.f / (1.f + expf(-ov));
            float u_ = tanhf(uv);
            float c = i_ * u_ + cr;
            float h = o_ * tanhf(c);
            out[n] = o_;
            out[HH + n] = c;
            out[2 * HH + n] = h;
        }
    }
}

// ============================================================================
extern "C" void kernel_launch(void* const* d_in, const int* in_sizes, int n_in,
                              void* d_out, int out_size) {
    const float* input      = (const float*)d_in[0];
    const float* children_c = (const float*)d_in[1];
    const float* children_h = (const float*)d_in[2];
    const float* W_iou_x    = (const float*)d_in[3];
    const float* b_iou_x    = (const float*)d_in[4];
    const float* W_iou_h    = (const float*)d_in[5];
    const float* b_iou_h    = (const float*)d_in[6];
    const float* W_fx       = (const float*)d_in[7];
    const float* b_fx       = (const float*)d_in[8];
    const float* W_fh       = (const float*)d_in[9];
    const float* b_fh       = (const float*)d_in[10];
    float* out = (float*)d_out;

    cudaFuncSetAttribute(k_gemm, cudaFuncAttributeMaxDynamicSharedMemorySize, SMEM_TOTAL_G);

    k_prep<<<dim3(8, 256), 256>>>(children_h, W_fh);
    k_gemm<<<dim3(16, 32), 256, SMEM_TOTAL_G>>>(children_c, b_fh,
                                                input, W_iou_x, b_iou_x,
                                                W_iou_h, b_iou_h, W_fx, b_fx, out);
}

// round 14
// speedup vs baseline: 1.1057x; 1.0120x over previous
#include <cuda_runtime.h>
#include <cuda_fp16.h>
#include <cstdint>

// ---------------- problem constants ----------------
#define DD 2048
#define HH 2048
#define KK 4096

// ---------------- scratch (device globals; no allocation allowed) ----------
__device__ __half g_hA[(size_t)KK * HH];        // children_h in fp16 (16MB)
__device__ __half g_hB[(size_t)HH * HH];        // W_fh in fp16 (8MB)
__device__ float  g_hsum_part[128][HH];
__device__ float  g_iou[3 * HH];
__device__ float  g_fx[HH];
__device__ float  g_cpart[32][HH];              // per-M-tile partial c sums
__device__ int    g_flags[64];                  // gemv strip ready flags
__device__ int    g_cnt[16];                    // per-bx completion counters

// ---------------- PTX helpers ----------------
__device__ __forceinline__ uint32_t smem_u32(const void* p) {
    uint32_t a;
    asm("{ .reg .u64 t; cvta.to.shared.u64 t, %1; cvt.u32.u64 %0, t; }" : "=r"(a) : "l"(p));
    return a;
}

#define CP_ASYNC16(dst, src) \
    asm volatile("cp.async.cg.shared.global [%0], [%1], 16;" :: "r"(dst), "l"(src))
#define CP_COMMIT() asm volatile("cp.async.commit_group;")
#define CP_WAIT(n)  asm volatile("cp.async.wait_group %0;" :: "n"(n))

#define LDSM_X4(r0, r1, r2, r3, addr) \
    asm volatile("ldmatrix.sync.aligned.m8n8.x4.shared.b16 {%0,%1,%2,%3}, [%4];" \
        : "=r"(r0), "=r"(r1), "=r"(r2), "=r"(r3) : "r"(addr))

#define MMA16816(d, a, b0, b1) \
    asm volatile("mma.sync.aligned.m16n8k16.row.col.f32.f16.f16.f32 " \
        "{%0,%1,%2,%3},{%4,%5,%6,%7},{%8,%9},{%0,%1,%2,%3};" \
        : "+f"((d)[0]), "+f"((d)[1]), "+f"((d)[2]), "+f"((d)[3]) \
        : "r"((a)[0]), "r"((a)[1]), "r"((a)[2]), "r"((a)[3]), "r"(b0), "r"(b1))

// ============================================================================
// Kernel 1: merged prep, 2048 blocks, MLP-4 batched loads.
//  by < 128 : column-sum partials of children_h (32-row strips) + fp16 convert
//  by >= 128: W_fh fp32->fp16 convert (1024 blocks, 4 float4/thread, batched)
// grid (8, 256), 256 threads
// ============================================================================
__global__ __launch_bounds__(256) void k_prep(const float* __restrict__ ch,
                                              const float* __restrict__ W) {
    int t = threadIdx.x;
    if (blockIdx.y < 128) {
        int cs = blockIdx.x, rs = blockIdx.y;
        int tx = t & 63, ty = t >> 6;
        int col = cs * 256 + tx * 4;
        int row0 = rs * 32 + ty * 8;
        float4 acc = make_float4(0.f, 0.f, 0.f, 0.f);
        // two 4-deep load batches (front-batched LDG -> MLP 4)
#pragma unroll
        for (int half = 0; half < 2; half++) {
            float4 v[4];
#pragma unroll
            for (int r = 0; r < 4; r++) {
                size_t off = (size_t)(row0 + half * 4 + r) * HH + col;
                v[r] = *reinterpret_cast<const float4*>(ch + off);
            }
#pragma unroll
            for (int r = 0; r < 4; r++) {
                size_t off = (size_t)(row0 + half * 4 + r) * HH + col;
                acc.x += v[r].x; acc.y += v[r].y; acc.z += v[r].z; acc.w += v[r].w;
                union { __half2 h2[2]; uint2 u; } cv;
                cv.h2[0] = __floats2half2_rn(v[r].x, v[r].y);
                cv.h2[1] = __floats2half2_rn(v[r].z, v[r].w);
                *reinterpret_cast<uint2*>(g_hA + off) = cv.u;
            }
        }
        __shared__ float sp[4][256];
        sp[ty][tx * 4 + 0] = acc.x;
        sp[ty][tx * 4 + 1] = acc.y;
        sp[ty][tx * 4 + 2] = acc.z;
        sp[ty][tx * 4 + 3] = acc.w;
        __syncthreads();
        float s = sp[0][t] + sp[1][t] + sp[2][t] + sp[3][t];
        g_hsum_part[rs][cs * 256 + t] = s;
    } else {
        int pb = blockIdx.x + 8 * (blockIdx.y - 128);    // 0..1023
        if (pb == 0 && t < 80) {
            if (t < 64) g_flags[t] = 0;
            else        g_cnt[t - 64] = 0;
        }
        float4 v[4];
#pragma unroll
        for (int k = 0; k < 4; k++)
            v[k] = reinterpret_cast<const float4*>(W)[pb * 1024 + k * 256 + t];
#pragma unroll
        for (int k = 0; k < 4; k++) {
            union { __half2 h2[2]; uint2 u; } cv;
            cv.h2[0] = __floats2half2_rn(v[k].x, v[k].y);
            cv.h2[1] = __floats2half2_rn(v[k].z, v[k].w);
            reinterpret_cast<uint2*>(g_hB)[pb * 1024 + k * 256 + t] = cv.u;
        }
    }
}

// ============================================================================
// Kernel 2: HMMA fp16 GEMM fh = children_h @ W_fh^T fused with
//   c_partial[n] += sum_m sigmoid(fx+b_fh+fh[m][n]) * children_c[m][n]
// R10 config byte-exact: BM=128, BN=128, BK=64 XOR-swizzled 128B rows,
// warp tile 32x64 (8 warps 4m x 2n), 2 CTAs/SM, NST=3, single-buffered
// fragments (measured at ~94% of the mma.sync fp32-acc tensor roofline).
// Grid (16 nT, 32 mT). First 64 CTAs (by<4) run the embedded GEMV producer
// prologue; last finisher per bx (counter==31) runs the final combine.
// ============================================================================
#define STB 32768                    // stage bytes: A 16KB + B 16KB
#define NST 3
#define SRED_OFF (NST * STB)         // 98304
#define FXS_OFF  (SRED_OFF + 4 * 128 * 4)
#define SMEM_TOTAL_G (FXS_OFF + 128 * 4)

__global__ __launch_bounds__(256, 2) void k_gemm(const float* __restrict__ children_c,
                                                 const float* __restrict__ bfh,
                                                 const float* __restrict__ input,
                                                 const float* __restrict__ Wix,
                                                 const float* __restrict__ bix,
                                                 const float* __restrict__ Wih,
                                                 const float* __restrict__ bih,
                                                 const float* __restrict__ Wfx,
                                                 const float* __restrict__ bfx,
                                                 float* __restrict__ out) {
    extern __shared__ __align__(1024) char smem[];
    __shared__ int s_old;
    uint32_t smb = smem_u32(smem);
    int t = threadIdx.x;
    int lane = t & 31, wid = t >> 5;
    int wm = wid & 3, wn = wid >> 2;
    int n0 = blockIdx.x * 128;
    int m0 = blockIdx.y * 128;

    // ------------- embedded GEMV producer prologue -------------
    if (blockIdx.y < 4) {
        int p = blockIdx.x + 16 * blockIdx.y;            // strip 0..63
        float* s_vec = reinterpret_cast<float*>(smem);   // input  [0,2048)
        float* s_hv  = reinterpret_cast<float*>(smem) + 2048;
        for (int i = t; i < 512; i += 256)
            reinterpret_cast<float4*>(s_vec)[i] = reinterpret_cast<const float4*>(input)[i];
        bool is_iou = (p < 48);
        if (is_iou) {
            for (int c = t; c < 2048; c += 256) {
                float s = 0.f;
#pragma unroll
                for (int r = 0; r < 128; r++) s += g_hsum_part[r][c];
                s_hv[c] = s;
            }
        }
        __syncthreads();
        int rbase = p * 128 + wid * 16;
        const float4* xi = reinterpret_cast<const float4*>(s_vec);
        const float4* xh = reinterpret_cast<const float4*>(s_hv);
#pragma unroll 1
        for (int rr = 0; rr < 16; rr += 2) {
            int R = rbase + rr;
            float acc0 = 0.f, acc1 = 0.f;
            if (is_iou) {
                const float4* w1a = reinterpret_cast<const float4*>(Wix + (size_t)R * DD);
                const float4* w1b = reinterpret_cast<const float4*>(Wix + (size_t)(R + 1) * DD);
                const float4* w2a = reinterpret_cast<const float4*>(Wih + (size_t)R * HH);
                const float4* w2b = reinterpret_cast<const float4*>(Wih + (size_t)(R + 1) * HH);
#pragma unroll
                for (int q = 0; q < 16; q++) {
                    float4 b = xi[q * 32 + lane];
                    float4 a0 = w1a[q * 32 + lane];
                    float4 a1 = w1b[q * 32 + lane];
                    acc0 += a0.x * b.x + a0.y * b.y + a0.z * b.z + a0.w * b.w;
                    acc1 += a1.x * b.x + a1.y * b.y + a1.z * b.z + a1.w * b.w;
                }
#pragma unroll
                for (int q = 0; q < 16; q++) {
                    float4 b = xh[q * 32 + lane];
                    float4 a0 = w2a[q * 32 + lane];
                    float4 a1 = w2b[q * 32 + lane];
                    acc0 += a0.x * b.x + a0.y * b.y + a0.z * b.z + a0.w * b.w;
                    acc1 += a1.x * b.x + a1.y * b.y + a1.z * b.z + a1.w * b.w;
                }
            } else {
                int j = R - 3 * HH;
                const float4* wa = reinterpret_cast<const float4*>(Wfx + (size_t)j * DD);
                const float4* wb = reinterpret_cast<const float4*>(Wfx + (size_t)(j + 1) * DD);
#pragma unroll
                for (int q = 0; q < 16; q++) {
                    float4 b = xi[q * 32 + lane];
                    float4 a0 = wa[q * 32 + lane];
                    float4 a1 = wb[q * 32 + lane];
                    acc0 += a0.x * b.x + a0.y * b.y + a0.z * b.z + a0.w * b.w;
                    acc1 += a1.x * b.x + a1.y * b.y + a1.z * b.z + a1.w * b.w;
                }
            }
#pragma unroll
            for (int off = 16; off; off >>= 1) {
                acc0 += __shfl_xor_sync(0xFFFFFFFFu, acc0, off);
                acc1 += __shfl_xor_sync(0xFFFFFFFFu, acc1, off);
            }
            if (lane == 0) {
                if (is_iou) {
                    g_iou[R]     = acc0 + bix[R] + bih[R];
                    g_iou[R + 1] = acc1 + bix[R + 1] + bih[R + 1];
                } else {
                    int j = R - 3 * HH;
                    g_fx[j]     = acc0 + bfx[j];
                    g_fx[j + 1] = acc1 + bfx[j + 1];
                }
            }
        }
        __threadfence();
        __syncthreads();
        if (t == 0) atomicExch(&g_flags[p], 1);
        __syncthreads();      // smem about to be reused by pipeline
    }

    // ------------- MMA mainloop (BK=64, swizzled 128B rows) -------------
    int rx = lane & 7;                 // row & 7 for all fragment rows
    int cA = lane >> 4;                // A: which 16B half of k16
    int cB = (lane >> 3) & 1;          // B: which 16B half of k16

    uint32_t aroff[2], broff[4];
#pragma unroll
    for (int mf = 0; mf < 2; mf++)
        aroff[mf] = (uint32_t)((wm * 32 + mf * 16 + (lane & 15)) << 7);
#pragma unroll
    for (int g = 0; g < 4; g++)
        broff[g] = (uint32_t)(16384 + ((wn * 64 + g * 16 + ((lane >> 4) << 3) + (lane & 7)) << 7));

    auto issue_load = [&](int ci, int s) {
        uint32_t st = smb + s * STB;
#pragma unroll
        for (int j = 0; j < 4; j++) {
            int idx = j * 256 + t;
            int r = idx >> 3, c = idx & 7;
            uint32_t off = (uint32_t)(r << 7) + (uint32_t)(((c ^ (r & 7))) << 4);
            const __half* srcA = g_hA + (size_t)(m0 + r) * HH + ci * 64 + c * 8;
            CP_ASYNC16(st + off, __cvta_generic_to_global(srcA));
            const __half* srcB = g_hB + (size_t)(n0 + r) * HH + ci * 64 + c * 8;
            CP_ASYNC16(st + 16384 + off, __cvta_generic_to_global(srcB));
        }
        CP_COMMIT();
    };

    float acc[2][8][4];
#pragma unroll
    for (int mf = 0; mf < 2; mf++)
#pragma unroll
        for (int nf = 0; nf < 8; nf++)
#pragma unroll
            for (int q = 0; q < 4; q++) acc[mf][nf][q] = 0.f;

    issue_load(0, 0);
    issue_load(1, 1);

    int s = 0;
    for (int ci = 0; ci < 32; ci++) {
        CP_WAIT(1);
        __syncthreads();
        if (ci + 2 < 32) {
            int s2 = s + 2; if (s2 >= 3) s2 -= 3;
            issue_load(ci + 2, s2);
        } else CP_COMMIT();

        uint32_t stb = smb + (uint32_t)s * STB;
#pragma unroll
        for (int kk = 0; kk < 4; kk++) {
            uint32_t offA = (uint32_t)(((kk * 2 + cA) ^ rx) << 4);
            uint32_t offB = (uint32_t)(((kk * 2 + cB) ^ rx) << 4);
            uint32_t ar[2][4];
            LDSM_X4(ar[0][0], ar[0][1], ar[0][2], ar[0][3], stb + aroff[0] + offA);
            LDSM_X4(ar[1][0], ar[1][1], ar[1][2], ar[1][3], stb + aroff[1] + offA);
            uint32_t br[4][4];
#pragma unroll
            for (int g = 0; g < 4; g++)
                LDSM_X4(br[g][0], br[g][1], br[g][2], br[g][3], stb + broff[g] + offB);
#pragma unroll
            for (int mf = 0; mf < 2; mf++)
#pragma unroll
                for (int nf = 0; nf < 8; nf++) {
                    int g = nf >> 1, h = (nf & 1) * 2;
                    MMA16816(acc[mf][nf], ar[mf], br[g][h], br[g][h + 1]);
                }
        }
        if (++s >= 3) s -= 3;
    }

    // ------------- fused epilogue -------------
    __syncthreads();
    // wait for the fx strip covering columns [n0, n0+128)
    if (t == 0) {
        while (atomicAdd(&g_flags[48 + blockIdx.x], 0) == 0) {}
        __threadfence();
    }
    __syncthreads();

    float* sred = reinterpret_cast<float*>(smem + SRED_OFF);
    float* fxs  = reinterpret_cast<float*>(smem + FXS_OFF);
    if (t < 128) fxs[t] = g_fx[n0 + t] + bfh[n0 + t];
    __syncthreads();

    int r0 = lane >> 2, q = lane & 3;
    float colsum[8][2];
#pragma unroll
    for (int nf = 0; nf < 8; nf++) { colsum[nf][0] = 0.f; colsum[nf][1] = 0.f; }

    const float* cbase = children_c + (size_t)(m0 + wm * 32) * HH + n0 + wn * 64;
#pragma unroll
    for (int mf = 0; mf < 2; mf++) {
        int rA = mf * 16 + r0;
        int rB = rA + 8;
#pragma unroll
        for (int nf = 0; nf < 8; nf++) {
            int cl = nf * 8 + q * 2;
            float2 ccA = *reinterpret_cast<const float2*>(cbase + (size_t)rA * HH + cl);
            float2 ccB = *reinterpret_cast<const float2*>(cbase + (size_t)rB * HH + cl);
            float fx0 = fxs[wn * 64 + cl];
            float fx1 = fxs[wn * 64 + cl + 1];
            const float* a = acc[mf][nf];
            float f00 = __fdividef(1.f, 1.f + __expf(-(fx0 + a[0])));
            float f01 = __fdividef(1.f, 1.f + __expf(-(fx1 + a[1])));
            float f10 = __fdividef(1.f, 1.f + __expf(-(fx0 + a[2])));
            float f11 = __fdividef(1.f, 1.f + __expf(-(fx1 + a[3])));
            colsum[nf][0] += f00 * ccA.x + f10 * ccB.x;
            colsum[nf][1] += f01 * ccA.y + f11 * ccB.y;
        }
    }
#pragma unroll
    for (int nf = 0; nf < 8; nf++) {
#pragma unroll
        for (int msk = 4; msk <= 16; msk <<= 1) {
            colsum[nf][0] += __shfl_xor_sync(0xFFFFFFFFu, colsum[nf][0], msk);
            colsum[nf][1] += __shfl_xor_sync(0xFFFFFFFFu, colsum[nf][1], msk);
        }
        if (lane < 4) {
            sred[wm * 128 + wn * 64 + nf * 8 + lane * 2 + 0] = colsum[nf][0];
            sred[wm * 128 + wn * 64 + nf * 8 + lane * 2 + 1] = colsum[nf][1];
        }
    }
    __syncthreads();
    if (t < 128) {
        float v = sred[t] + sred[128 + t] + sred[256 + t] + sred[384 + t];
        g_cpart[blockIdx.y][n0 + t] = v;
    }
    __threadfence();
    __syncthreads();
    if (t == 0) s_old = atomicAdd(&g_cnt[blockIdx.x], 1);
    __syncthreads();

    // ------------- final combine (last finisher per bx) -------------
    if (s_old == 31) {
        if (t == 0) {
            while (atomicAdd(&g_flags[blockIdx.x], 0) == 0) {}
            while (atomicAdd(&g_flags[16 + blockIdx.x], 0) == 0) {}
            while (atomicAdd(&g_flags[32 + blockIdx.x], 0) == 0) {}
            __threadfence();
        }
        __syncthreads();
        if (t < 128) {
            int n = n0 + t;
            float cr = 0.f;
#pragma unroll
            for (int r = 0; r < 32; r++) cr += g_cpart[r][n];
            float iv = g_iou[n];
            float ov = g_iou[HH + n];
            float uv = g_iou[2 * HH + n];
            float i_ = 1.f / (1.f + expf(-iv));
            float o_ = 1.f / (1.f + expf(-ov));
            float u_ = tanhf(uv);
            float c = i_ * u_ + cr;
            float h = o_ * tanhf(c);
            out[n] = o_;
            out[HH + n] = c;
            out[2 * HH + n] = h;
        }
    }
}

// ============================================================================
extern "C" void kernel_launch(void* const* d_in, const int* in_sizes, int n_in,
                              void* d_out, int out_size) {
    const float* input      = (const float*)d_in[0];
    const float* children_c = (const float*)d_in[1];
    const float* children_h = (const float*)d_in[2];
    const float* W_iou_x    = (const float*)d_in[3];
    const float* b_iou_x    = (const float*)d_in[4];
    const float* W_iou_h    = (const float*)d_in[5];
    const float* b_iou_h    = (const float*)d_in[6];
    const float* W_fx       = (const float*)d_in[7];
    const float* b_fx       = (const float*)d_in[8];
    const float* W_fh       = (const float*)d_in[9];
    const float* b_fh       = (const float*)d_in[10];
    float* out = (float*)d_out;

    cudaFuncSetAttribute(k_gemm, cudaFuncAttributeMaxDynamicSharedMemorySize, SMEM_TOTAL_G);

    k_prep<<<dim3(8, 256), 256>>>(children_h, W_fh);
    k_gemm<<<dim3(16, 32), 256, SMEM_TOTAL_G>>>(children_c, b_fh,
                                                input, W_iou_x, b_iou_x,
                                                W_iou_h, b_iou_h, W_fx, b_fx, out);
}